// round 11
// baseline (speedup 1.0000x reference)
#include <cuda_runtime.h>
#include <cuda.h>
#include <cuda_fp16.h>
#include <cstdint>

// ---------------- problem constants ----------------
#define BATCH  16384
#define IN_DIM 1024
#define HDIM   4096

#define TM 64
#define TN 128
#define TK 128                // per-chunk K (two 64-wide SW128 subtiles)
#define STAGES 2
#define NCOLT (HDIM / TN)     // 32 column tiles
#define NTILES (NCOLT * (BATCH / TM))   // 8192
#define NCTA   296            // 2 CTAs/SM x 148 SMs (fully resident, persistent)

#define SUB_A     8192        // 64 rows x 64 fp16 (128B rows)
#define SUB_B     16384       // 128 rows x 64 fp16
#define STAGE_SZ  49152       // A0 A1 B0 B1
#define TILES_OFF 4096
#define SMEM_DYN  (TILES_OFF + STAGES * STAGE_SZ)   // 102400 -> 2 CTAs/SM

#define NWARP_C 4             // compute warps (1x4 grid, 64x32 warp tile)
#define NTHREADS (NWARP_C * 32 + 32)   // + producer warp = 160

// smem front layout
#define MB_FULL   8           // 2 x 8B
#define MB_EMPTY  32          // 2 x 8B
#define OFF_RED   64          // 64 x 4 floats = 1024B (ends 1088 < 4096)

// ---------------- device scratch ----------------
__device__ __half g_x [(size_t)BATCH * IN_DIM];
__device__ __half g_s1[(size_t)HDIM * IN_DIM];
__device__ __half g_s2[(size_t)HDIM * HDIM];
__device__ __half g_h [(size_t)BATCH * HDIM];
__device__ float  g_part[(size_t)NCOLT * BATCH];

// ---------------- PTX helpers (portable: sm_90 base) ----------------
__device__ __forceinline__ uint32_t smem_u32(const void* p) {
    uint32_t a;
    asm("{ .reg .u64 t; cvta.to.shared.u64 t, %1; cvt.u32.u64 %0, t; }"
        : "=r"(a) : "l"(p));
    return a;
}

#define MBAR_INIT(addr, cnt) \
    asm volatile("mbarrier.init.shared.b64 [%0], %1;" :: "r"(addr), "r"((uint32_t)(cnt)) : "memory")
#define MBAR_ARRIVE(addr) \
    asm volatile("mbarrier.arrive.shared.b64 _, [%0];" :: "r"(addr) : "memory")
#define MBAR_EXPECT_TX(addr, bytes) \
    asm volatile("mbarrier.arrive.expect_tx.shared.b64 _, [%0], %1;" :: "r"(addr), "r"((uint32_t)(bytes)) : "memory")

// Orders this thread's prior generic-proxy smem reads (ldmatrix) before the
// producer's async-proxy (TMA) overwrite. REQUIRED before empty-arrive.
#define FENCE_ASYNC_SHARED() \
    asm volatile("fence.proxy.async.shared::cta;" ::: "memory")

#define MBAR_WAIT(addr, parity) do {                                               \
    uint32_t _m = (addr); uint32_t _p = (uint32_t)(parity); uint32_t _d;           \
    asm volatile(                                                                   \
        "{\n\t.reg .pred p;\n\t"                                                    \
        "mbarrier.try_wait.parity.shared.b64 p, [%1], %2;\n\t"                      \
        "selp.b32 %0, 1, 0, p;\n\t}"                                                \
        : "=r"(_d) : "r"(_m), "r"(_p) : "memory");                                  \
    if (!_d) {                                                                      \
        asm volatile(                                                               \
            "{\n\t.reg .pred P1;\n\t"                                               \
            "WL_%=:\n\t"                                                            \
            "mbarrier.try_wait.parity.shared.b64 P1, [%0], %1;\n\t"                 \
            "@P1 bra.uni WD_%=;\n\t"                                                \
            "bra.uni WL_%=;\n\t"                                                    \
            "WD_%=:\n\t}"                                                           \
            :: "r"(_m), "r"(_p) : "memory");                                        \
    }                                                                               \
} while (0)

#define TMA_LOAD_3D(smem_addr, tm, cx, cy, cz, mbar)                                \
    asm volatile(                                                                   \
        "cp.async.bulk.tensor.3d.shared::cluster.global.tile.mbarrier::complete_tx::bytes " \
        "[%0], [%1, {%2, %3, %4}], [%5];"                                           \
        :: "r"((uint32_t)(smem_addr)), "l"((const void*)(tm)),                      \
           "r"((int)(cx)), "r"((int)(cy)), "r"((int)(cz)),                          \
           "r"((uint32_t)(mbar)) : "memory")

#define LDSM_X4(r0, r1, r2, r3, addr)                                               \
    asm volatile("ldmatrix.sync.aligned.m8n8.x4.shared.b16 {%0,%1,%2,%3}, [%4];"    \
                 : "=r"(r0), "=r"(r1), "=r"(r2), "=r"(r3) : "r"(addr))

#define MMA16816(d, a0, a1, a2, a3, b0, b1)                                         \
    asm volatile(                                                                   \
        "mma.sync.aligned.m16n8k16.row.col.f32.f16.f16.f32 "                        \
        "{%0,%1,%2,%3},{%4,%5,%6,%7},{%8,%9},{%0,%1,%2,%3};"                        \
        : "+f"((d)[0]), "+f"((d)[1]), "+f"((d)[2]), "+f"((d)[3])                    \
        : "r"(a0), "r"(a1), "r"(a2), "r"(a3), "r"(b0), "r"(b1))

// consumer-warps-only barrier (producer warp excluded)
#define CONS_BAR() asm volatile("bar.sync 1, 128;" ::: "memory")

// ---------------- prologue kernels ----------------
__global__ void convert_x_kernel(const float* __restrict__ x, int n) {
    int i = blockIdx.x * blockDim.x + threadIdx.x;
    if (i < n) g_x[i] = __float2half_rn(x[i]);
}
__global__ void convert_state_kernel(const int* __restrict__ s,
                                     __half* __restrict__ dst, int n) {
    int i = blockIdx.x * blockDim.x + threadIdx.x;
    if (i < n) dst[i] = __float2half_rn((float)s[i]);   // {-1,0,1} exact
}
__global__ void head_reduce_kernel(const float* __restrict__ b_out,
                                   float* __restrict__ out) {
    int r = blockIdx.x * blockDim.x + threadIdx.x;
    if (r >= BATCH) return;
    float s = b_out[0];
#pragma unroll
    for (int t = 0; t < NCOLT; t++) s += g_part[(size_t)t * BATCH + r];
    out[r] = s;
}

// per-column epilogue constants, loaded from gmem (L2-hot) at epilogue time
__device__ __forceinline__ float softplus_scale(const float* __restrict__ ls, int j) {
    float z  = ls[j];
    float sp = fmaxf(z, 0.f) + log1pf(expf(-fabsf(z)));
    return fmaxf(sp, 1e-4f);
}

// ---------------- persistent fused ternary GEMM (portable mma.sync) ----------------
// 4 compute warps (64x32 tiles) + 1 TMA producer warp; 2 CTAs/SM; grid = 296.
// Each CTA strides over tiles; the TMA ring never drains (global chunk counter).
template <bool L2K>
__global__ void __launch_bounds__(NTHREADS, 2)
gemm_kernel(const __grid_constant__ CUtensorMap dA,
            const __grid_constant__ CUtensorMap dB,
            const float* __restrict__ log_scale,
            const float* __restrict__ bias,
            const float* __restrict__ w_out,
            int K) {
    extern __shared__ char smem_raw[];
    const uint32_t sb = smem_u32(smem_raw);
    const int tid  = threadIdx.x;
    const int wid  = tid >> 5;
    const int lane = tid & 31;
    const int nc = K / TK;

    float* red = (float*)(smem_raw + OFF_RED);
    const uint32_t tiles = sb + TILES_OFF;

    if (tid == 0) {
#pragma unroll
        for (int s = 0; s < STAGES; s++) {
            MBAR_INIT(sb + MB_FULL  + 8 * s, 1);
            MBAR_INIT(sb + MB_EMPTY + 8 * s, NWARP_C * 32);
        }
        FENCE_ASYNC_SHARED();
    }
    __syncthreads();

    if (wid == NWARP_C) {
        // ---------------- dedicated TMA producer warp ----------------
        if (lane == 0) {
            int c = 0;                         // global chunk counter
            for (int tile = blockIdx.x; tile < NTILES; tile += NCTA) {
                const int n0 = (tile & (NCOLT - 1)) * TN;
                const int m0 = (tile / NCOLT) * TM;
                for (int k = 0; k < nc; k++, c++) {
                    const int s = c & 1;
                    uint32_t full  = sb + MB_FULL  + 8 * s;
                    uint32_t empty = sb + MB_EMPTY + 8 * s;
                    if (c >= 2) MBAR_WAIT(empty, ((c >> 1) - 1) & 1);
                    MBAR_EXPECT_TX(full, STAGE_SZ);
                    uint32_t st = tiles + s * STAGE_SZ;
                    TMA_LOAD_3D(st,                 &dA, k * TK,      m0, 0, full);
                    TMA_LOAD_3D(st + SUB_A,         &dA, k * TK + 64, m0, 0, full);
                    TMA_LOAD_3D(st + 2 * SUB_A,         &dB, k * TK,      n0, 0, full);
                    TMA_LOAD_3D(st + 2 * SUB_A + SUB_B, &dB, k * TK + 64, n0, 0, full);
                }
            }
        }
    } else {
        // ---------------- compute warps 0..3 (1x4, 64x32 tiles) ----------------
        const int wn = wid;             // 0..3 (N)

        const int aHi = lane >> 4;
        const int bHi = (lane >> 3) & 1;
        uint32_t aBase[4]; int aS7[4];
#pragma unroll
        for (int mf = 0; mf < 4; mf++) {
            int r = mf * 16 + (lane & 15);
            aBase[mf] = (uint32_t)(r * 128);
            aS7[mf]   = r & 7;
        }
        uint32_t bBase[2]; int bS7[2];
#pragma unroll
        for (int p = 0; p < 2; p++) {
            int r = wn * 32 + p * 16 + ((lane >> 4) << 3) + (lane & 7);
            bBase[p] = (uint32_t)(r * 128);
            bS7[p]   = r & 7;
        }
        const int q4 = lane >> 2;            // 0..7
        const int c2 = (lane & 3) * 2;       // 0,2,4,6

        int c = 0;                           // global chunk counter
        for (int tile = blockIdx.x; tile < NTILES; tile += NCTA) {
            const int n0 = (tile & (NCOLT - 1)) * TN;
            const int m0 = (tile / NCOLT) * TM;

            float acc[4][4][4];
#pragma unroll
            for (int i = 0; i < 4; i++)
#pragma unroll
                for (int j = 0; j < 4; j++)
#pragma unroll
                    for (int q = 0; q < 4; q++) acc[i][j][q] = 0.f;

            for (int k = 0; k < nc; ++k, ++c) {
                const int s  = c & 1;
                const uint32_t st = tiles + s * STAGE_SZ;
                MBAR_WAIT(sb + MB_FULL + 8 * s, (c >> 1) & 1);

#pragma unroll
                for (int ks8 = 0; ks8 < 8; ks8++) {
                    const int sub = ks8 >> 2;
                    const int ksl = ks8 & 3;
                    const uint32_t aT = st + sub * SUB_A;
                    const uint32_t bT = st + 2 * SUB_A + sub * SUB_B;
                    uint32_t b[2][4];
#pragma unroll
                    for (int p = 0; p < 2; p++) {
                        uint32_t ad = bT + bBase[p] + (uint32_t)((((ksl * 2 + bHi) ^ bS7[p])) << 4);
                        LDSM_X4(b[p][0], b[p][1], b[p][2], b[p][3], ad);
                    }
                    uint32_t a[4][4];
#pragma unroll
                    for (int mf = 0; mf < 4; mf++) {
                        uint32_t ad = aT + aBase[mf] + (uint32_t)((((ksl * 2 + aHi) ^ aS7[mf])) << 4);
                        LDSM_X4(a[mf][0], a[mf][1], a[mf][2], a[mf][3], ad);
                    }
#pragma unroll
                    for (int mf = 0; mf < 4; mf++)
#pragma unroll
                        for (int nf = 0; nf < 4; nf++)
                            MMA16816(acc[mf][nf],
                                     a[mf][0], a[mf][1], a[mf][2], a[mf][3],
                                     b[nf >> 1][(nf & 1) * 2], b[nf >> 1][(nf & 1) * 2 + 1]);
                }
                FENCE_ASYNC_SHARED();          // race fix: order LDSMs before TMA reuse
                MBAR_ARRIVE(sb + MB_EMPTY + 8 * s);
            }

            // ---------------- epilogue (per-element math identical to R10) ----------------
#pragma unroll
            for (int mf = 0; mf < 4; mf++) {
                float pr0 = 0.f, pr1 = 0.f;
                const int rL0 = mf * 16 + q4;
#pragma unroll
                for (int nf = 0; nf < 4; nf++) {
                    const int lc = wn * 32 + nf * 8 + c2;
                    const int j  = n0 + lc;
                    float s0 = softplus_scale(log_scale, j);
                    float s1 = softplus_scale(log_scale, j + 1);
                    float bi0 = bias[j], bi1 = bias[j + 1];
                    float y0 = fminf(1.f, fmaxf(-1.f, fmaf(acc[mf][nf][0], s0, bi0)));
                    float y1 = fminf(1.f, fmaxf(-1.f, fmaf(acc[mf][nf][1], s1, bi1)));
                    float y2 = fminf(1.f, fmaxf(-1.f, fmaf(acc[mf][nf][2], s0, bi0)));
                    float y3 = fminf(1.f, fmaxf(-1.f, fmaf(acc[mf][nf][3], s1, bi1)));
                    if (L2K) {
                        float w0 = w_out[j], w1 = w_out[j + 1];
                        pr0 = fmaf(y0, w0, fmaf(y1, w1, pr0));
                        pr1 = fmaf(y2, w0, fmaf(y3, w1, pr1));
                    } else {
                        __half2 h01 = __floats2half2_rn(y0, y1);
                        __half2 h23 = __floats2half2_rn(y2, y3);
                        size_t base0 = (size_t)(m0 + rL0)     * HDIM + j;
                        size_t base1 = (size_t)(m0 + rL0 + 8) * HDIM + j;
                        *reinterpret_cast<__half2*>(g_h + base0) = h01;
                        *reinterpret_cast<__half2*>(g_h + base1) = h23;
                    }
                }
                if (L2K) {
                    pr0 += __shfl_xor_sync(0xffffffffu, pr0, 1);
                    pr0 += __shfl_xor_sync(0xffffffffu, pr0, 2);
                    pr1 += __shfl_xor_sync(0xffffffffu, pr1, 1);
                    pr1 += __shfl_xor_sync(0xffffffffu, pr1, 2);
                    if ((lane & 3) == 0) {
                        red[(rL0)     * 4 + wn] = pr0;
                        red[(rL0 + 8) * 4 + wn] = pr1;
                    }
                }
            }
            if (L2K) {
                CONS_BAR();                     // red writes visible (consumer warps only)
                if (tid < TM) {
                    float s = red[tid * 4 + 0] + red[tid * 4 + 1] +
                              red[tid * 4 + 2] + red[tid * 4 + 3];
                    g_part[(size_t)(n0 / TN) * BATCH + m0 + tid] = s;
                }
                CONS_BAR();                     // reads done before next tile's writes
            }
        }
    }
}

// ---------------- host launcher ----------------
typedef CUresult (*PFN_encodeTiled)(CUtensorMap*, CUtensorMapDataType, cuuint32_t,
                                    void*, const cuuint64_t*, const cuuint64_t*,
                                    const cuuint32_t*, const cuuint32_t*,
                                    CUtensorMapInterleave, CUtensorMapSwizzle,
                                    CUtensorMapL2promotion, CUtensorMapFloatOOBfill);

static void make_tmap(PFN_encodeTiled enc, CUtensorMap* m, void* ptr,
                      long long K, long long rows, unsigned box1) {
    cuuint64_t dims[3]    = {(cuuint64_t)K, (cuuint64_t)rows, 1};
    cuuint64_t strides[2] = {(cuuint64_t)(K * 2), (cuuint64_t)(K * rows * 2)};
    cuuint32_t box[3]     = {64, box1, 1};
    cuuint32_t es[3]      = {1, 1, 1};
    enc(m, CU_TENSOR_MAP_DATA_TYPE_FLOAT16, 3, ptr, dims, strides, box, es,
        CU_TENSOR_MAP_INTERLEAVE_NONE, CU_TENSOR_MAP_SWIZZLE_128B,
        CU_TENSOR_MAP_L2_PROMOTION_L2_128B, CU_TENSOR_MAP_FLOAT_OOB_FILL_NONE);
}

extern "C" void kernel_launch(void* const* d_in, const int* in_sizes, int n_in,
                              void* d_out, int out_size) {
    const float* x   = (const float*)d_in[0];
    const int*   st1 = (const int*)  d_in[1];
    const float* ls1 = (const float*)d_in[2];
    const float* b1  = (const float*)d_in[3];
    const int*   st2 = (const int*)  d_in[4];
    const float* ls2 = (const float*)d_in[5];
    const float* b2  = (const float*)d_in[6];
    const float* wo  = (const float*)d_in[7];
    const float* bo  = (const float*)d_in[8];
    float*       out = (float*)d_out;

    void *p_x, *p_s1, *p_s2, *p_h;
    cudaGetSymbolAddress(&p_x,  g_x);
    cudaGetSymbolAddress(&p_s1, g_s1);
    cudaGetSymbolAddress(&p_s2, g_s2);
    cudaGetSymbolAddress(&p_h,  g_h);

    PFN_encodeTiled enc = nullptr;
    cudaDriverEntryPointQueryResult qr;
    cudaGetDriverEntryPoint("cuTensorMapEncodeTiled", (void**)&enc,
                            cudaEnableDefault, &qr);
    if (!enc) return;

    CUtensorMap dA1, dB1, dA2, dB2;
    make_tmap(enc, &dA1, p_x,  IN_DIM, BATCH, TM);
    make_tmap(enc, &dB1, p_s1, IN_DIM, HDIM,  TN);
    make_tmap(enc, &dA2, p_h,  HDIM,   BATCH, TM);
    make_tmap(enc, &dB2, p_s2, HDIM,   HDIM,  TN);

    cudaFuncSetAttribute(gemm_kernel<false>,
                         cudaFuncAttributeMaxDynamicSharedMemorySize, SMEM_DYN);
    cudaFuncSetAttribute(gemm_kernel<true>,
                         cudaFuncAttributeMaxDynamicSharedMemorySize, SMEM_DYN);

    convert_x_kernel<<<(BATCH * IN_DIM) / 256, 256>>>(x, BATCH * IN_DIM);
    convert_state_kernel<<<(HDIM * IN_DIM) / 256, 256>>>(st1, (__half*)p_s1,
                                                         HDIM * IN_DIM);
    convert_state_kernel<<<(HDIM * HDIM) / 256, 256>>>(st2, (__half*)p_s2,
                                                       HDIM * HDIM);

    gemm_kernel<false><<<NCTA, NTHREADS, SMEM_DYN>>>(dA1, dB1, ls1, b1, nullptr, IN_DIM);
    gemm_kernel<true ><<<NCTA, NTHREADS, SMEM_DYN>>>(dA2, dB2, ls2, b2, wo,      HDIM);

    head_reduce_kernel<<<BATCH / 256, 256>>>(bo, out);
}

// round 12
// speedup vs baseline: 1.0199x; 1.0199x over previous
#include <cuda_runtime.h>
#include <cuda.h>
#include <cuda_fp16.h>
#include <cstdint>

// ---------------- problem constants ----------------
#define BATCH  16384
#define IN_DIM 1024
#define HDIM   4096

#define TM 128
#define TN 128
#define TK 64                 // per-chunk K (one 64-wide SW128 subtile)
#define STAGES 3
#define NCOLT (HDIM / TN)     // 32 column tiles

#define SUB_A     16384       // 128 rows x 64 fp16 (128B rows)
#define STAGE_SZ  32768       // A + B
#define TILES_OFF 4096
#define SMEM_DYN  (TILES_OFF + STAGES * STAGE_SZ)   // 102400 -> 2 CTAs/SM

#define NWARP_C 8             // compute warps (2x4 grid, 64x32 warp tile)
#define NTHREADS (NWARP_C * 32 + 32)   // + producer warp = 288

// smem front layout
#define MB_FULL   8           // 3 x 8B
#define MB_EMPTY  32          // 3 x 8B
#define OFF_SCALE 128         // 128 floats
#define OFF_BIAS  640
#define OFF_W     1152
#define OFF_RED   1664        // 128 x 4 floats -> ends 3712 (< 4096)

// ---------------- device scratch ----------------
__device__ __half g_x [(size_t)BATCH * IN_DIM];
__device__ __half g_s1[(size_t)HDIM * IN_DIM];
__device__ __half g_s2[(size_t)HDIM * HDIM];
__device__ __half g_h [(size_t)BATCH * HDIM];
__device__ float  g_part[(size_t)NCOLT * BATCH];

// ---------------- PTX helpers (portable: sm_90 base) ----------------
__device__ __forceinline__ uint32_t smem_u32(const void* p) {
    uint32_t a;
    asm("{ .reg .u64 t; cvta.to.shared.u64 t, %1; cvt.u32.u64 %0, t; }"
        : "=r"(a) : "l"(p));
    return a;
}

#define MBAR_INIT(addr, cnt) \
    asm volatile("mbarrier.init.shared.b64 [%0], %1;" :: "r"(addr), "r"((uint32_t)(cnt)) : "memory")
#define MBAR_ARRIVE(addr) \
    asm volatile("mbarrier.arrive.shared.b64 _, [%0];" :: "r"(addr) : "memory")
#define MBAR_EXPECT_TX(addr, bytes) \
    asm volatile("mbarrier.arrive.expect_tx.shared.b64 _, [%0], %1;" :: "r"(addr), "r"((uint32_t)(bytes)) : "memory")

// Orders this thread's prior generic-proxy smem reads (ldmatrix) before the
// producer's async-proxy (TMA) overwrite. REQUIRED before empty-arrive.
#define FENCE_ASYNC_SHARED() \
    asm volatile("fence.proxy.async.shared::cta;" ::: "memory")

#define MBAR_WAIT(addr, parity) do {                                               \
    uint32_t _m = (addr); uint32_t _p = (uint32_t)(parity); uint32_t _d;           \
    asm volatile(                                                                   \
        "{\n\t.reg .pred p;\n\t"                                                    \
        "mbarrier.try_wait.parity.shared.b64 p, [%1], %2;\n\t"                      \
        "selp.b32 %0, 1, 0, p;\n\t}"                                                \
        : "=r"(_d) : "r"(_m), "r"(_p) : "memory");                                  \
    if (!_d) {                                                                      \
        asm volatile(                                                               \
            "{\n\t.reg .pred P1;\n\t"                                               \
            "WL_%=:\n\t"                                                            \
            "mbarrier.try_wait.parity.shared.b64 P1, [%0], %1;\n\t"                 \
            "@P1 bra.uni WD_%=;\n\t"                                                \
            "bra.uni WL_%=;\n\t"                                                    \
            "WD_%=:\n\t}"                                                           \
            :: "r"(_m), "r"(_p) : "memory");                                        \
    }                                                                               \
} while (0)

#define TMA_LOAD_3D(smem_addr, tm, cx, cy, cz, mbar)                                \
    asm volatile(                                                                   \
        "cp.async.bulk.tensor.3d.shared::cluster.global.tile.mbarrier::complete_tx::bytes " \
        "[%0], [%1, {%2, %3, %4}], [%5];"                                           \
        :: "r"((uint32_t)(smem_addr)), "l"((const void*)(tm)),                      \
           "r"((int)(cx)), "r"((int)(cy)), "r"((int)(cz)),                          \
           "r"((uint32_t)(mbar)) : "memory")

#define LDSM_X4(r0, r1, r2, r3, addr)                                               \
    asm volatile("ldmatrix.sync.aligned.m8n8.x4.shared.b16 {%0,%1,%2,%3}, [%4];"    \
                 : "=r"(r0), "=r"(r1), "=r"(r2), "=r"(r3) : "r"(addr))

#define MMA16816(d, a0, a1, a2, a3, b0, b1)                                         \
    asm volatile(                                                                   \
        "mma.sync.aligned.m16n8k16.row.col.f32.f16.f16.f32 "                        \
        "{%0,%1,%2,%3},{%4,%5,%6,%7},{%8,%9},{%0,%1,%2,%3};"                        \
        : "+f"((d)[0]), "+f"((d)[1]), "+f"((d)[2]), "+f"((d)[3])                    \
        : "r"(a0), "r"(a1), "r"(a2), "r"(a3), "r"(b0), "r"(b1))

// ---------------- prologue kernels ----------------
__global__ void convert_x_kernel(const float* __restrict__ x, int n) {
    int i = blockIdx.x * blockDim.x + threadIdx.x;
    if (i < n) g_x[i] = __float2half_rn(x[i]);
}
__global__ void convert_state_kernel(const int* __restrict__ s,
                                     __half* __restrict__ dst, int n) {
    int i = blockIdx.x * blockDim.x + threadIdx.x;
    if (i < n) dst[i] = __float2half_rn((float)s[i]);   // {-1,0,1} exact
}
__global__ void head_reduce_kernel(const float* __restrict__ b_out,
                                   float* __restrict__ out) {
    int r = blockIdx.x * blockDim.x + threadIdx.x;
    if (r >= BATCH) return;
    float s = b_out[0];
#pragma unroll
    for (int t = 0; t < NCOLT; t++) s += g_part[(size_t)t * BATCH + r];
    out[r] = s;
}

// ---------------- fused ternary GEMM (portable mma.sync) ----------------
// TM=128/TN=128/TK=64, 3 stages, 2 CTAs/SM. 8 compute warps (2x4, 64x32
// warp tiles) + 1 TMA producer warp. Proxy-fence race fix included.
// Epilogue: y = clamp(softplus_scale[n]*acc + bias[n], -1, 1)
//   L2K=false: store y (fp16) into g_h
//   L2K=true : per-row partial += y * w_out[n]; write g_part[bx][row]
template <bool L2K>
__global__ void __launch_bounds__(NTHREADS, 2)
gemm_kernel(const __grid_constant__ CUtensorMap dA,
            const __grid_constant__ CUtensorMap dB,
            const float* __restrict__ log_scale,
            const float* __restrict__ bias,
            const float* __restrict__ w_out,
            int K) {
    extern __shared__ char smem_raw[];
    const uint32_t sb = smem_u32(smem_raw);
    const int tid  = threadIdx.x;
    const int wid  = tid >> 5;
    const int lane = tid & 31;
    const int m0 = blockIdx.y * TM;
    const int n0 = blockIdx.x * TN;
    const int nc = K / TK;

    float* scale_s = (float*)(smem_raw + OFF_SCALE);
    float* bias_s  = (float*)(smem_raw + OFF_BIAS);
    float* w_s     = (float*)(smem_raw + OFF_W);
    float* red     = (float*)(smem_raw + OFF_RED);
    const uint32_t tiles = sb + TILES_OFF;

    if (tid == 0) {
#pragma unroll
        for (int s = 0; s < STAGES; s++) {
            MBAR_INIT(sb + MB_FULL  + 8 * s, 1);
            MBAR_INIT(sb + MB_EMPTY + 8 * s, NWARP_C * 32);
        }
        FENCE_ASYNC_SHARED();
    }
    if (tid < TN) {
        int j = n0 + tid;
        float z  = log_scale[j];
        float sp = fmaxf(z, 0.f) + log1pf(expf(-fabsf(z)));
        scale_s[tid] = fmaxf(sp, 1e-4f);
        bias_s[tid]  = bias[j];
        if (L2K) w_s[tid] = w_out[j];
    }
    __syncthreads();

    if (wid == NWARP_C) {
        // ---------------- dedicated TMA producer warp ----------------
        if (lane == 0) {
            for (int k = 0; k < nc; k++) {
                int i = k / STAGES;
                int s = k - i * STAGES;
                uint32_t full  = sb + MB_FULL  + 8 * s;
                uint32_t empty = sb + MB_EMPTY + 8 * s;
                if (i > 0) MBAR_WAIT(empty, (i - 1) & 1);
                MBAR_EXPECT_TX(full, STAGE_SZ);
                uint32_t st = tiles + s * STAGE_SZ;
                TMA_LOAD_3D(st,         &dA, k * TK, m0, 0, full);
                TMA_LOAD_3D(st + SUB_A, &dB, k * TK, n0, 0, full);
            }
        }
    } else {
        // ---------------- compute warps 0..7 (2x4, 64x32 tiles) ----------------
        const int wm = wid >> 2;        // 0..1 (M)
        const int wn = wid & 3;         // 0..3 (N)

        const int aHi = lane >> 4;
        const int bHi = (lane >> 3) & 1;
        uint32_t aBase[4]; int aS7[4];
#pragma unroll
        for (int mf = 0; mf < 4; mf++) {
            int r = wm * 64 + mf * 16 + (lane & 15);
            aBase[mf] = (uint32_t)(r * 128);
            aS7[mf]   = r & 7;
        }
        uint32_t bBase[2]; int bS7[2];
#pragma unroll
        for (int p = 0; p < 2; p++) {
            int r = wn * 32 + p * 16 + ((lane >> 4) << 3) + (lane & 7);
            bBase[p] = (uint32_t)(SUB_A + r * 128);
            bS7[p]   = r & 7;
        }

        float acc[4][4][4];
#pragma unroll
        for (int i = 0; i < 4; i++)
#pragma unroll
            for (int j = 0; j < 4; j++)
#pragma unroll
                for (int q = 0; q < 4; q++) acc[i][j][q] = 0.f;

        for (int k = 0; k < nc; ++k) {
            const int s  = k % STAGES;
            const int ph = (k / STAGES) & 1;
            const uint32_t st = tiles + s * STAGE_SZ;
            MBAR_WAIT(sb + MB_FULL + 8 * s, ph);

#pragma unroll
            for (int ks = 0; ks < 4; ks++) {
                uint32_t b[2][4];
#pragma unroll
                for (int p = 0; p < 2; p++) {
                    uint32_t ad = st + bBase[p] + (uint32_t)((((ks * 2 + bHi) ^ bS7[p])) << 4);
                    LDSM_X4(b[p][0], b[p][1], b[p][2], b[p][3], ad);
                }
                uint32_t a[4][4];
#pragma unroll
                for (int mf = 0; mf < 4; mf++) {
                    uint32_t ad = st + aBase[mf] + (uint32_t)((((ks * 2 + aHi) ^ aS7[mf])) << 4);
                    LDSM_X4(a[mf][0], a[mf][1], a[mf][2], a[mf][3], ad);
                }
#pragma unroll
                for (int mf = 0; mf < 4; mf++)
#pragma unroll
                    for (int nf = 0; nf < 4; nf++)
                        MMA16816(acc[mf][nf],
                                 a[mf][0], a[mf][1], a[mf][2], a[mf][3],
                                 b[nf >> 1][(nf & 1) * 2], b[nf >> 1][(nf & 1) * 2 + 1]);
            }
            FENCE_ASYNC_SHARED();          // race fix: order LDSMs before TMA reuse
            MBAR_ARRIVE(sb + MB_EMPTY + 8 * s);
        }

        // ---------------- epilogue ----------------
        const int q4 = lane >> 2;            // 0..7
        const int c2 = (lane & 3) * 2;       // 0,2,4,6
#pragma unroll
        for (int mf = 0; mf < 4; mf++) {
            float pr0 = 0.f, pr1 = 0.f;
            const int rL0 = wm * 64 + mf * 16 + q4;       // local rows rL0, rL0+8
#pragma unroll
            for (int nf = 0; nf < 4; nf++) {
                const int lc = wn * 32 + nf * 8 + c2;     // local col (even)
                float s0 = scale_s[lc], s1 = scale_s[lc + 1];
                float bi0 = bias_s[lc], bi1 = bias_s[lc + 1];
                float y0 = fminf(1.f, fmaxf(-1.f, fmaf(acc[mf][nf][0], s0, bi0)));
                float y1 = fminf(1.f, fmaxf(-1.f, fmaf(acc[mf][nf][1], s1, bi1)));
                float y2 = fminf(1.f, fmaxf(-1.f, fmaf(acc[mf][nf][2], s0, bi0)));
                float y3 = fminf(1.f, fmaxf(-1.f, fmaf(acc[mf][nf][3], s1, bi1)));
                if (L2K) {
                    float w0 = w_s[lc], w1 = w_s[lc + 1];
                    pr0 = fmaf(y0, w0, fmaf(y1, w1, pr0));
                    pr1 = fmaf(y2, w0, fmaf(y3, w1, pr1));
                } else {
                    __half2 h01 = __floats2half2_rn(y0, y1);
                    __half2 h23 = __floats2half2_rn(y2, y3);
                    size_t base0 = (size_t)(m0 + rL0)     * HDIM + n0 + lc;
                    size_t base1 = (size_t)(m0 + rL0 + 8) * HDIM + n0 + lc;
                    *reinterpret_cast<__half2*>(g_h + base0) = h01;
                    *reinterpret_cast<__half2*>(g_h + base1) = h23;
                }
            }
            if (L2K) {
                pr0 += __shfl_xor_sync(0xffffffffu, pr0, 1);
                pr0 += __shfl_xor_sync(0xffffffffu, pr0, 2);
                pr1 += __shfl_xor_sync(0xffffffffu, pr1, 1);
                pr1 += __shfl_xor_sync(0xffffffffu, pr1, 2);
                if ((lane & 3) == 0) {
                    red[(rL0)     * 4 + wn] = pr0;
                    red[(rL0 + 8) * 4 + wn] = pr1;
                }
            }
        }
    }
    if (L2K) {
        __syncthreads();
        if (tid < TM) {
            float s = red[tid * 4 + 0] + red[tid * 4 + 1] +
                      red[tid * 4 + 2] + red[tid * 4 + 3];
            g_part[(size_t)blockIdx.x * BATCH + m0 + tid] = s;
        }
    }
}

// ---------------- host launcher ----------------
typedef CUresult (*PFN_encodeTiled)(CUtensorMap*, CUtensorMapDataType, cuuint32_t,
                                    void*, const cuuint64_t*, const cuuint64_t*,
                                    const cuuint32_t*, const cuuint32_t*,
                                    CUtensorMapInterleave, CUtensorMapSwizzle,
                                    CUtensorMapL2promotion, CUtensorMapFloatOOBfill);

static void make_tmap(PFN_encodeTiled enc, CUtensorMap* m, void* ptr,
                      long long K, long long rows, unsigned box1) {
    cuuint64_t dims[3]    = {(cuuint64_t)K, (cuuint64_t)rows, 1};
    cuuint64_t strides[2] = {(cuuint64_t)(K * 2), (cuuint64_t)(K * rows * 2)};
    cuuint32_t box[3]     = {64, box1, 1};
    cuuint32_t es[3]      = {1, 1, 1};
    enc(m, CU_TENSOR_MAP_DATA_TYPE_FLOAT16, 3, ptr, dims, strides, box, es,
        CU_TENSOR_MAP_INTERLEAVE_NONE, CU_TENSOR_MAP_SWIZZLE_128B,
        CU_TENSOR_MAP_L2_PROMOTION_L2_128B, CU_TENSOR_MAP_FLOAT_OOB_FILL_NONE);
}

extern "C" void kernel_launch(void* const* d_in, const int* in_sizes, int n_in,
                              void* d_out, int out_size) {
    const float* x   = (const float*)d_in[0];
    const int*   st1 = (const int*)  d_in[1];
    const float* ls1 = (const float*)d_in[2];
    const float* b1  = (const float*)d_in[3];
    const int*   st2 = (const int*)  d_in[4];
    const float* ls2 = (const float*)d_in[5];
    const float* b2  = (const float*)d_in[6];
    const float* wo  = (const float*)d_in[7];
    const float* bo  = (const float*)d_in[8];
    float*       out = (float*)d_out;

    void *p_x, *p_s1, *p_s2, *p_h;
    cudaGetSymbolAddress(&p_x,  g_x);
    cudaGetSymbolAddress(&p_s1, g_s1);
    cudaGetSymbolAddress(&p_s2, g_s2);
    cudaGetSymbolAddress(&p_h,  g_h);

    PFN_encodeTiled enc = nullptr;
    cudaDriverEntryPointQueryResult qr;
    cudaGetDriverEntryPoint("cuTensorMapEncodeTiled", (void**)&enc,
                            cudaEnableDefault, &qr);
    if (!enc) return;

    CUtensorMap dA1, dB1, dA2, dB2;
    make_tmap(enc, &dA1, p_x,  IN_DIM, BATCH, TM);
    make_tmap(enc, &dB1, p_s1, IN_DIM, HDIM,  TN);
    make_tmap(enc, &dA2, p_h,  HDIM,   BATCH, TM);
    make_tmap(enc, &dB2, p_s2, HDIM,   HDIM,  TN);

    cudaFuncSetAttribute(gemm_kernel<false>,
                         cudaFuncAttributeMaxDynamicSharedMemorySize, SMEM_DYN);
    cudaFuncSetAttribute(gemm_kernel<true>,
                         cudaFuncAttributeMaxDynamicSharedMemorySize, SMEM_DYN);

    convert_x_kernel<<<(BATCH * IN_DIM) / 256, 256>>>(x, BATCH * IN_DIM);
    convert_state_kernel<<<(HDIM * IN_DIM) / 256, 256>>>(st1, (__half*)p_s1,
                                                         HDIM * IN_DIM);
    convert_state_kernel<<<(HDIM * HDIM) / 256, 256>>>(st2, (__half*)p_s2,
                                                       HDIM * HDIM);

    dim3 grid(NCOLT, BATCH / TM);   // (32, 128)
    gemm_kernel<false><<<grid, NTHREADS, SMEM_DYN>>>(dA1, dB1, ls1, b1, nullptr, IN_DIM);
    gemm_kernel<true ><<<grid, NTHREADS, SMEM_DYN>>>(dA2, dB2, ls2, b2, wo,      HDIM);

    head_reduce_kernel<<<BATCH / 256, 256>>>(bo, out);
}

// round 13
// speedup vs baseline: 1.0440x; 1.0236x over previous
#include <cuda_runtime.h>
#include <cuda.h>
#include <cuda_fp16.h>
#include <cstdint>

// ---------------- problem constants ----------------
#define BATCH  16384
#define IN_DIM 1024
#define HDIM   4096

#define TM 64
#define TN 128
#define TK 64                 // per-chunk K (one 64-wide SW128 subtile)
#define STAGES 2
#define NCOLT (HDIM / TN)     // 32 column tiles

#define SUB_A     8192        // 64 rows x 64 fp16 (128B rows)
#define STAGE_SZ  24576       // A(8K) + B(16K)
#define TILES_OFF 4096
#define SMEM_DYN  (TILES_OFF + STAGES * STAGE_SZ)   // 53248 -> 3 CTAs/SM

#define NWARP_C 4             // compute warps (1x4 grid, 64x32 warp tile)
#define NTHREADS (NWARP_C * 32 + 32)   // + producer warp = 160

// smem front layout
#define MB_FULL   8           // 2 x 8B
#define MB_EMPTY  32          // 2 x 8B
#define OFF_SCALE 128
#define OFF_BIAS  640
#define OFF_W     1152
#define OFF_RED   1664        // 64 x 4 floats -> ends 2688 (< 4096)

// ---------------- device scratch ----------------
__device__ __half g_x [(size_t)BATCH * IN_DIM];
__device__ __half g_s1[(size_t)HDIM * IN_DIM];
__device__ __half g_s2[(size_t)HDIM * HDIM];
__device__ __half g_h [(size_t)BATCH * HDIM];
__device__ float  g_part[(size_t)NCOLT * BATCH];

// ---------------- PTX helpers (portable: sm_90 base) ----------------
__device__ __forceinline__ uint32_t smem_u32(const void* p) {
    uint32_t a;
    asm("{ .reg .u64 t; cvta.to.shared.u64 t, %1; cvt.u32.u64 %0, t; }"
        : "=r"(a) : "l"(p));
    return a;
}

#define MBAR_INIT(addr, cnt) \
    asm volatile("mbarrier.init.shared.b64 [%0], %1;" :: "r"(addr), "r"((uint32_t)(cnt)) : "memory")
#define MBAR_ARRIVE(addr) \
    asm volatile("mbarrier.arrive.shared.b64 _, [%0];" :: "r"(addr) : "memory")
#define MBAR_EXPECT_TX(addr, bytes) \
    asm volatile("mbarrier.arrive.expect_tx.shared.b64 _, [%0], %1;" :: "r"(addr), "r"((uint32_t)(bytes)) : "memory")

// Orders this thread's prior generic-proxy smem reads (ldmatrix) before the
// producer's async-proxy (TMA) overwrite. REQUIRED before empty-arrive.
#define FENCE_ASYNC_SHARED() \
    asm volatile("fence.proxy.async.shared::cta;" ::: "memory")

#define MBAR_WAIT(addr, parity) do {                                               \
    uint32_t _m = (addr); uint32_t _p = (uint32_t)(parity); uint32_t _d;           \
    asm volatile(                                                                   \
        "{\n\t.reg .pred p;\n\t"                                                    \
        "mbarrier.try_wait.parity.shared.b64 p, [%1], %2;\n\t"                      \
        "selp.b32 %0, 1, 0, p;\n\t}"                                                \
        : "=r"(_d) : "r"(_m), "r"(_p) : "memory");                                  \
    if (!_d) {                                                                      \
        asm volatile(                                                               \
            "{\n\t.reg .pred P1;\n\t"                                               \
            "WL_%=:\n\t"                                                            \
            "mbarrier.try_wait.parity.shared.b64 P1, [%0], %1;\n\t"                 \
            "@P1 bra.uni WD_%=;\n\t"                                                \
            "bra.uni WL_%=;\n\t"                                                    \
            "WD_%=:\n\t}"                                                           \
            :: "r"(_m), "r"(_p) : "memory");                                        \
    }                                                                               \
} while (0)

#define TMA_LOAD_3D(smem_addr, tm, cx, cy, cz, mbar)                                \
    asm volatile(                                                                   \
        "cp.async.bulk.tensor.3d.shared::cluster.global.tile.mbarrier::complete_tx::bytes " \
        "[%0], [%1, {%2, %3, %4}], [%5];"                                           \
        :: "r"((uint32_t)(smem_addr)), "l"((const void*)(tm)),                      \
           "r"((int)(cx)), "r"((int)(cy)), "r"((int)(cz)),                          \
           "r"((uint32_t)(mbar)) : "memory")

#define LDSM_X4(r0, r1, r2, r3, addr)                                               \
    asm volatile("ldmatrix.sync.aligned.m8n8.x4.shared.b16 {%0,%1,%2,%3}, [%4];"    \
                 : "=r"(r0), "=r"(r1), "=r"(r2), "=r"(r3) : "r"(addr))

#define MMA16816(d, a0, a1, a2, a3, b0, b1)                                         \
    asm volatile(                                                                   \
        "mma.sync.aligned.m16n8k16.row.col.f32.f16.f16.f32 "                        \
        "{%0,%1,%2,%3},{%4,%5,%6,%7},{%8,%9},{%0,%1,%2,%3};"                        \
        : "+f"((d)[0]), "+f"((d)[1]), "+f"((d)[2]), "+f"((d)[3])                    \
        : "r"(a0), "r"(a1), "r"(a2), "r"(a3), "r"(b0), "r"(b1))

// ---------------- prologue kernels ----------------
__global__ void convert_x_kernel(const float* __restrict__ x, int n) {
    int i = blockIdx.x * blockDim.x + threadIdx.x;
    if (i < n) g_x[i] = __float2half_rn(x[i]);
}
__global__ void convert_state_kernel(const int* __restrict__ s,
                                     __half* __restrict__ dst, int n) {
    int i = blockIdx.x * blockDim.x + threadIdx.x;
    if (i < n) dst[i] = __float2half_rn((float)s[i]);   // {-1,0,1} exact
}
__global__ void head_reduce_kernel(const float* __restrict__ b_out,
                                   float* __restrict__ out) {
    int r = blockIdx.x * blockDim.x + threadIdx.x;
    if (r >= BATCH) return;
    float s = b_out[0];
#pragma unroll
    for (int t = 0; t < NCOLT; t++) s += g_part[(size_t)t * BATCH + r];
    out[r] = s;
}

// ---------------- fused ternary GEMM (portable mma.sync) ----------------
// TM=64/TN=128/TK=64, 2 stages, 3 CTAs/SM. 4 compute warps (64x32 tiles)
// + 1 TMA producer warp. Proxy-fence race fix included.
// Epilogue: y = clamp(softplus_scale[n]*acc + bias[n], -1, 1)
//   L2K=false: store y (fp16) into g_h
//   L2K=true : per-row partial += y * w_out[n]; write g_part[bx][row]
template <bool L2K>
__global__ void __launch_bounds__(NTHREADS, 3)
gemm_kernel(const __grid_constant__ CUtensorMap dA,
            const __grid_constant__ CUtensorMap dB,
            const float* __restrict__ log_scale,
            const float* __restrict__ bias,
            const float* __restrict__ w_out,
            int K) {
    extern __shared__ char smem_raw[];
    const uint32_t sb = smem_u32(smem_raw);
    const int tid  = threadIdx.x;
    const int wid  = tid >> 5;
    const int lane = tid & 31;
    const int m0 = blockIdx.y * TM;
    const int n0 = blockIdx.x * TN;
    const int nc = K / TK;

    float* scale_s = (float*)(smem_raw + OFF_SCALE);
    float* bias_s  = (float*)(smem_raw + OFF_BIAS);
    float* w_s     = (float*)(smem_raw + OFF_W);
    float* red     = (float*)(smem_raw + OFF_RED);
    const uint32_t tiles = sb + TILES_OFF;

    if (tid == 0) {
#pragma unroll
        for (int s = 0; s < STAGES; s++) {
            MBAR_INIT(sb + MB_FULL  + 8 * s, 1);
            MBAR_INIT(sb + MB_EMPTY + 8 * s, NWARP_C * 32);
        }
        FENCE_ASYNC_SHARED();
    }
    if (tid < TN) {
        int j = n0 + tid;
        float z  = log_scale[j];
        float sp = fmaxf(z, 0.f) + log1pf(expf(-fabsf(z)));
        scale_s[tid] = fmaxf(sp, 1e-4f);
        bias_s[tid]  = bias[j];
        if (L2K) w_s[tid] = w_out[j];
    }
    __syncthreads();

    if (wid == NWARP_C) {
        // ---------------- dedicated TMA producer warp ----------------
        if (lane == 0) {
            for (int k = 0; k < nc; k++) {
                int i = k / STAGES;
                int s = k - i * STAGES;
                uint32_t full  = sb + MB_FULL  + 8 * s;
                uint32_t empty = sb + MB_EMPTY + 8 * s;
                if (i > 0) MBAR_WAIT(empty, (i - 1) & 1);
                MBAR_EXPECT_TX(full, STAGE_SZ);
                uint32_t st = tiles + s * STAGE_SZ;
                TMA_LOAD_3D(st,         &dA, k * TK, m0, 0, full);
                TMA_LOAD_3D(st + SUB_A, &dB, k * TK, n0, 0, full);
            }
        }
    } else {
        // ---------------- compute warps 0..3 (1x4, 64x32 tiles) ----------------
        const int wn = wid;             // 0..3 (N)

        const int aHi = lane >> 4;
        const int bHi = (lane >> 3) & 1;
        uint32_t aBase[4]; int aS7[4];
#pragma unroll
        for (int mf = 0; mf < 4; mf++) {
            int r = mf * 16 + (lane & 15);
            aBase[mf] = (uint32_t)(r * 128);
            aS7[mf]   = r & 7;
        }
        uint32_t bBase[2]; int bS7[2];
#pragma unroll
        for (int p = 0; p < 2; p++) {
            int r = wn * 32 + p * 16 + ((lane >> 4) << 3) + (lane & 7);
            bBase[p] = (uint32_t)(SUB_A + r * 128);
            bS7[p]   = r & 7;
        }

        float acc[4][4][4];
#pragma unroll
        for (int i = 0; i < 4; i++)
#pragma unroll
            for (int j = 0; j < 4; j++)
#pragma unroll
                for (int q = 0; q < 4; q++) acc[i][j][q] = 0.f;

        for (int k = 0; k < nc; ++k) {
            const int s  = k % STAGES;
            const int ph = (k / STAGES) & 1;
            const uint32_t st = tiles + s * STAGE_SZ;
            MBAR_WAIT(sb + MB_FULL + 8 * s, ph);

#pragma unroll
            for (int ks = 0; ks < 4; ks++) {
                uint32_t b[2][4];
#pragma unroll
                for (int p = 0; p < 2; p++) {
                    uint32_t ad = st + bBase[p] + (uint32_t)((((ks * 2 + bHi) ^ bS7[p])) << 4);
                    LDSM_X4(b[p][0], b[p][1], b[p][2], b[p][3], ad);
                }
                uint32_t a[4][4];
#pragma unroll
                for (int mf = 0; mf < 4; mf++) {
                    uint32_t ad = st + aBase[mf] + (uint32_t)((((ks * 2 + aHi) ^ aS7[mf])) << 4);
                    LDSM_X4(a[mf][0], a[mf][1], a[mf][2], a[mf][3], ad);
                }
#pragma unroll
                for (int mf = 0; mf < 4; mf++)
#pragma unroll
                    for (int nf = 0; nf < 4; nf++)
                        MMA16816(acc[mf][nf],
                                 a[mf][0], a[mf][1], a[mf][2], a[mf][3],
                                 b[nf >> 1][(nf & 1) * 2], b[nf >> 1][(nf & 1) * 2 + 1]);
            }
            FENCE_ASYNC_SHARED();          // race fix: order LDSMs before TMA reuse
            MBAR_ARRIVE(sb + MB_EMPTY + 8 * s);
        }

        // ---------------- epilogue ----------------
        const int q4 = lane >> 2;            // 0..7
        const int c2 = (lane & 3) * 2;       // 0,2,4,6
#pragma unroll
        for (int mf = 0; mf < 4; mf++) {
            float pr0 = 0.f, pr1 = 0.f;
            const int rL0 = mf * 16 + q4;                 // local rows rL0, rL0+8
#pragma unroll
            for (int nf = 0; nf < 4; nf++) {
                const int lc = wn * 32 + nf * 8 + c2;     // local col (even)
                float s0 = scale_s[lc], s1 = scale_s[lc + 1];
                float bi0 = bias_s[lc], bi1 = bias_s[lc + 1];
                float y0 = fminf(1.f, fmaxf(-1.f, fmaf(acc[mf][nf][0], s0, bi0)));
                float y1 = fminf(1.f, fmaxf(-1.f, fmaf(acc[mf][nf][1], s1, bi1)));
                float y2 = fminf(1.f, fmaxf(-1.f, fmaf(acc[mf][nf][2], s0, bi0)));
                float y3 = fminf(1.f, fmaxf(-1.f, fmaf(acc[mf][nf][3], s1, bi1)));
                if (L2K) {
                    float w0 = w_s[lc], w1 = w_s[lc + 1];
                    pr0 = fmaf(y0, w0, fmaf(y1, w1, pr0));
                    pr1 = fmaf(y2, w0, fmaf(y3, w1, pr1));
                } else {
                    __half2 h01 = __floats2half2_rn(y0, y1);
                    __half2 h23 = __floats2half2_rn(y2, y3);
                    size_t base0 = (size_t)(m0 + rL0)     * HDIM + n0 + lc;
                    size_t base1 = (size_t)(m0 + rL0 + 8) * HDIM + n0 + lc;
                    *reinterpret_cast<__half2*>(g_h + base0) = h01;
                    *reinterpret_cast<__half2*>(g_h + base1) = h23;
                }
            }
            if (L2K) {
                pr0 += __shfl_xor_sync(0xffffffffu, pr0, 1);
                pr0 += __shfl_xor_sync(0xffffffffu, pr0, 2);
                pr1 += __shfl_xor_sync(0xffffffffu, pr1, 1);
                pr1 += __shfl_xor_sync(0xffffffffu, pr1, 2);
                if ((lane & 3) == 0) {
                    red[(rL0)     * 4 + wn] = pr0;
                    red[(rL0 + 8) * 4 + wn] = pr1;
                }
            }
        }
    }
    if (L2K) {
        __syncthreads();
        if (tid < TM) {
            float s = red[tid * 4 + 0] + red[tid * 4 + 1] +
                      red[tid * 4 + 2] + red[tid * 4 + 3];
            g_part[(size_t)blockIdx.x * BATCH + m0 + tid] = s;
        }
    }
}

// ---------------- host launcher ----------------
typedef CUresult (*PFN_encodeTiled)(CUtensorMap*, CUtensorMapDataType, cuuint32_t,
                                    void*, const cuuint64_t*, const cuuint64_t*,
                                    const cuuint32_t*, const cuuint32_t*,
                                    CUtensorMapInterleave, CUtensorMapSwizzle,
                                    CUtensorMapL2promotion, CUtensorMapFloatOOBfill);

static void make_tmap(PFN_encodeTiled enc, CUtensorMap* m, void* ptr,
                      long long K, long long rows, unsigned box1) {
    cuuint64_t dims[3]    = {(cuuint64_t)K, (cuuint64_t)rows, 1};
    cuuint64_t strides[2] = {(cuuint64_t)(K * 2), (cuuint64_t)(K * rows * 2)};
    cuuint32_t box[3]     = {64, box1, 1};
    cuuint32_t es[3]      = {1, 1, 1};
    enc(m, CU_TENSOR_MAP_DATA_TYPE_FLOAT16, 3, ptr, dims, strides, box, es,
        CU_TENSOR_MAP_INTERLEAVE_NONE, CU_TENSOR_MAP_SWIZZLE_128B,
        CU_TENSOR_MAP_L2_PROMOTION_L2_128B, CU_TENSOR_MAP_FLOAT_OOB_FILL_NONE);
}

extern "C" void kernel_launch(void* const* d_in, const int* in_sizes, int n_in,
                              void* d_out, int out_size) {
    const float* x   = (const float*)d_in[0];
    const int*   st1 = (const int*)  d_in[1];
    const float* ls1 = (const float*)d_in[2];
    const float* b1  = (const float*)d_in[3];
    const int*   st2 = (const int*)  d_in[4];
    const float* ls2 = (const float*)d_in[5];
    const float* b2  = (const float*)d_in[6];
    const float* wo  = (const float*)d_in[7];
    const float* bo  = (const float*)d_in[8];
    float*       out = (float*)d_out;

    void *p_x, *p_s1, *p_s2, *p_h;
    cudaGetSymbolAddress(&p_x,  g_x);
    cudaGetSymbolAddress(&p_s1, g_s1);
    cudaGetSymbolAddress(&p_s2, g_s2);
    cudaGetSymbolAddress(&p_h,  g_h);

    PFN_encodeTiled enc = nullptr;
    cudaDriverEntryPointQueryResult qr;
    cudaGetDriverEntryPoint("cuTensorMapEncodeTiled", (void**)&enc,
                            cudaEnableDefault, &qr);
    if (!enc) return;

    CUtensorMap dA1, dB1, dA2, dB2;
    make_tmap(enc, &dA1, p_x,  IN_DIM, BATCH, TM);
    make_tmap(enc, &dB1, p_s1, IN_DIM, HDIM,  TN);
    make_tmap(enc, &dA2, p_h,  HDIM,   BATCH, TM);
    make_tmap(enc, &dB2, p_s2, HDIM,   HDIM,  TN);

    cudaFuncSetAttribute(gemm_kernel<false>,
                         cudaFuncAttributeMaxDynamicSharedMemorySize, SMEM_DYN);
    cudaFuncSetAttribute(gemm_kernel<true>,
                         cudaFuncAttributeMaxDynamicSharedMemorySize, SMEM_DYN);

    convert_x_kernel<<<(BATCH * IN_DIM) / 256, 256>>>(x, BATCH * IN_DIM);
    convert_state_kernel<<<(HDIM * IN_DIM) / 256, 256>>>(st1, (__half*)p_s1,
                                                         HDIM * IN_DIM);
    convert_state_kernel<<<(HDIM * HDIM) / 256, 256>>>(st2, (__half*)p_s2,
                                                       HDIM * HDIM);

    dim3 grid(NCOLT, BATCH / TM);   // (32, 256)
    gemm_kernel<false><<<grid, NTHREADS, SMEM_DYN>>>(dA1, dB1, ls1, b1, nullptr, IN_DIM);
    gemm_kernel<true ><<<grid, NTHREADS, SMEM_DYN>>>(dA2, dB2, ls2, b2, wo,      HDIM);

    head_reduce_kernel<<<BATCH / 256, 256>>>(bo, out);
}

// round 14
// speedup vs baseline: 1.1106x; 1.0638x over previous
#include <cuda_runtime.h>
#include <cuda.h>
#include <cuda_fp16.h>
#include <cstdint>

// ---------------- problem constants ----------------
#define BATCH  16384
#define IN_DIM 1024
#define HDIM   4096

#define TM 64
#define TN 128
#define NCOLT (HDIM / TN)     // 32 column tiles
#define NWARP_C 4             // compute warps (1x4 grid, 64x32 warp tile)
#define NTHREADS (NWARP_C * 32 + 32)   // + producer warp = 160

// ---- GEMM1 (TK=64, 2 stages, 3 CTAs/SM) ----
#define G1_TK     64
#define G1_SUB_A  8192        // 64 x 64 fp16 (128B rows)
#define G1_STAGE  24576       // A(8K) + B(16K)
#define G1_STAGES 2
#define G1_TILES  4096
#define G1_SMEM   (G1_TILES + G1_STAGES * G1_STAGE)   // 53248 -> 3 CTAs/SM

// ---- GEMM2 (TK=128, 2 stages, 2 CTAs/SM; R6 geometry) ----
#define G2_TK     128
#define G2_SUB_A  8192        // 64 x 64 fp16
#define G2_SUB_B  16384       // 128 x 64 fp16
#define G2_STAGE  49152       // A0 A1 B0 B1
#define G2_STAGES 2
#define G2_TILES  4096
#define G2_SMEM   (G2_TILES + G2_STAGES * G2_STAGE)   // 102400 -> 2 CTAs/SM

// smem front layout (both kernels)
#define MB_FULL   8           // 2 x 8B
#define MB_EMPTY  32          // 2 x 8B
#define OFF_SCALE 128
#define OFF_BIAS  640
#define OFF_W     1152
#define OFF_RED   1664        // 64 x 4 floats -> ends 2688 (< 4096)

// ---------------- device scratch ----------------
__device__ __half g_x [(size_t)BATCH * IN_DIM];
__device__ __half g_s1[(size_t)HDIM * IN_DIM];
__device__ __half g_s2[(size_t)HDIM * HDIM];
__device__ __half g_h [(size_t)BATCH * HDIM];
__device__ float  g_part[(size_t)NCOLT * BATCH];

// ---------------- PTX helpers (portable: sm_90 base) ----------------
__device__ __forceinline__ uint32_t smem_u32(const void* p) {
    uint32_t a;
    asm("{ .reg .u64 t; cvta.to.shared.u64 t, %1; cvt.u32.u64 %0, t; }"
        : "=r"(a) : "l"(p));
    return a;
}

#define MBAR_INIT(addr, cnt) \
    asm volatile("mbarrier.init.shared.b64 [%0], %1;" :: "r"(addr), "r"((uint32_t)(cnt)) : "memory")
#define MBAR_ARRIVE(addr) \
    asm volatile("mbarrier.arrive.shared.b64 _, [%0];" :: "r"(addr) : "memory")
#define MBAR_EXPECT_TX(addr, bytes) \
    asm volatile("mbarrier.arrive.expect_tx.shared.b64 _, [%0], %1;" :: "r"(addr), "r"((uint32_t)(bytes)) : "memory")

// Orders this thread's prior generic-proxy smem reads (ldmatrix) before the
// producer's async-proxy (TMA) overwrite. REQUIRED before empty-arrive.
#define FENCE_ASYNC_SHARED() \
    asm volatile("fence.proxy.async.shared::cta;" ::: "memory")

#define MBAR_WAIT(addr, parity) do {                                               \
    uint32_t _m = (addr); uint32_t _p = (uint32_t)(parity); uint32_t _d;           \
    asm volatile(                                                                   \
        "{\n\t.reg .pred p;\n\t"                                                    \
        "mbarrier.try_wait.parity.shared.b64 p, [%1], %2;\n\t"                      \
        "selp.b32 %0, 1, 0, p;\n\t}"                                                \
        : "=r"(_d) : "r"(_m), "r"(_p) : "memory");                                  \
    if (!_d) {                                                                      \
        asm volatile(                                                               \
            "{\n\t.reg .pred P1;\n\t"                                               \
            "WL_%=:\n\t"                                                            \
            "mbarrier.try_wait.parity.shared.b64 P1, [%0], %1;\n\t"                 \
            "@P1 bra.uni WD_%=;\n\t"                                                \
            "bra.uni WL_%=;\n\t"                                                    \
            "WD_%=:\n\t}"                                                           \
            :: "r"(_m), "r"(_p) : "memory");                                        \
    }                                                                               \
} while (0)

#define TMA_LOAD_3D(smem_addr, tm, cx, cy, cz, mbar)                                \
    asm volatile(                                                                   \
        "cp.async.bulk.tensor.3d.shared::cluster.global.tile.mbarrier::complete_tx::bytes " \
        "[%0], [%1, {%2, %3, %4}], [%5];"                                           \
        :: "r"((uint32_t)(smem_addr)), "l"((const void*)(tm)),                      \
           "r"((int)(cx)), "r"((int)(cy)), "r"((int)(cz)),                          \
           "r"((uint32_t)(mbar)) : "memory")

#define LDSM_X4(r0, r1, r2, r3, addr)                                               \
    asm volatile("ldmatrix.sync.aligned.m8n8.x4.shared.b16 {%0,%1,%2,%3}, [%4];"    \
                 : "=r"(r0), "=r"(r1), "=r"(r2), "=r"(r3) : "r"(addr))

#define MMA16816(d, a0, a1, a2, a3, b0, b1)                                         \
    asm volatile(                                                                   \
        "mma.sync.aligned.m16n8k16.row.col.f32.f16.f16.f32 "                        \
        "{%0,%1,%2,%3},{%4,%5,%6,%7},{%8,%9},{%0,%1,%2,%3};"                        \
        : "+f"((d)[0]), "+f"((d)[1]), "+f"((d)[2]), "+f"((d)[3])                    \
        : "r"(a0), "r"(a1), "r"(a2), "r"(a3), "r"(b0), "r"(b1))

// ---------------- fused, vectorized prologue ----------------
#define XN  (BATCH * IN_DIM)      // 16,777,216
#define S1N (HDIM * IN_DIM)       //  4,194,304
#define S2N (HDIM * HDIM)         // 16,777,216
#define CVT_QUADS ((XN + S1N + S2N) / 4)

struct half4 { __half a, b, c, d; };

__global__ void convert_all_kernel(const float* __restrict__ x,
                                   const int* __restrict__ s1,
                                   const int* __restrict__ s2) {
    long long i = (long long)blockIdx.x * blockDim.x + threadIdx.x;
    if (i >= CVT_QUADS) return;
    long long q = i * 4;
    half4 o;
    if (q < XN) {
        float4 v = *reinterpret_cast<const float4*>(x + q);
        o.a = __float2half_rn(v.x); o.b = __float2half_rn(v.y);
        o.c = __float2half_rn(v.z); o.d = __float2half_rn(v.w);
        *reinterpret_cast<half4*>(g_x + q) = o;
    } else if (q < XN + S1N) {
        long long j = q - XN;
        int4 v = *reinterpret_cast<const int4*>(s1 + j);
        o.a = __float2half_rn((float)v.x); o.b = __float2half_rn((float)v.y);
        o.c = __float2half_rn((float)v.z); o.d = __float2half_rn((float)v.w);
        *reinterpret_cast<half4*>(g_s1 + j) = o;
    } else {
        long long j = q - XN - S1N;
        int4 v = *reinterpret_cast<const int4*>(s2 + j);
        o.a = __float2half_rn((float)v.x); o.b = __float2half_rn((float)v.y);
        o.c = __float2half_rn((float)v.z); o.d = __float2half_rn((float)v.w);
        *reinterpret_cast<half4*>(g_s2 + j) = o;
    }
}

__global__ void head_reduce_kernel(const float* __restrict__ b_out,
                                   float* __restrict__ out) {
    int r = blockIdx.x * blockDim.x + threadIdx.x;
    if (r >= BATCH) return;
    float s = b_out[0];
#pragma unroll
    for (int t = 0; t < NCOLT; t++) s += g_part[(size_t)t * BATCH + r];
    out[r] = s;
}

// ---------------- GEMM1: TK=64, 2 stages, 3 CTAs/SM (R13-validated) ----------------
// h1 = clamp(softplus_scale[n]*acc + bias[n], -1, 1) -> g_h fp16
__global__ void __launch_bounds__(NTHREADS, 3)
gemm1_kernel(const __grid_constant__ CUtensorMap dA,
             const __grid_constant__ CUtensorMap dB,
             const float* __restrict__ log_scale,
             const float* __restrict__ bias,
             int K) {
    extern __shared__ char smem_raw[];
    const uint32_t sb = smem_u32(smem_raw);
    const int tid  = threadIdx.x;
    const int wid  = tid >> 5;
    const int lane = tid & 31;
    const int m0 = blockIdx.y * TM;
    const int n0 = blockIdx.x * TN;
    const int nc = K / G1_TK;

    float* scale_s = (float*)(smem_raw + OFF_SCALE);
    float* bias_s  = (float*)(smem_raw + OFF_BIAS);
    const uint32_t tiles = sb + G1_TILES;

    if (tid == 0) {
#pragma unroll
        for (int s = 0; s < G1_STAGES; s++) {
            MBAR_INIT(sb + MB_FULL  + 8 * s, 1);
            MBAR_INIT(sb + MB_EMPTY + 8 * s, NWARP_C * 32);
        }
        FENCE_ASYNC_SHARED();
    }
    if (tid < TN) {
        int j = n0 + tid;
        float z  = log_scale[j];
        float sp = fmaxf(z, 0.f) + log1pf(expf(-fabsf(z)));
        scale_s[tid] = fmaxf(sp, 1e-4f);
        bias_s[tid]  = bias[j];
    }
    __syncthreads();

    if (wid == NWARP_C) {
        if (lane == 0) {
            for (int k = 0; k < nc; k++) {
                int i = k / G1_STAGES;
                int s = k - i * G1_STAGES;
                uint32_t full  = sb + MB_FULL  + 8 * s;
                uint32_t empty = sb + MB_EMPTY + 8 * s;
                if (i > 0) MBAR_WAIT(empty, (i - 1) & 1);
                MBAR_EXPECT_TX(full, G1_STAGE);
                uint32_t st = tiles + s * G1_STAGE;
                TMA_LOAD_3D(st,            &dA, k * G1_TK, m0, 0, full);
                TMA_LOAD_3D(st + G1_SUB_A, &dB, k * G1_TK, n0, 0, full);
            }
        }
    } else {
        const int wn = wid;             // 0..3 (N)

        const int aHi = lane >> 4;
        const int bHi = (lane >> 3) & 1;
        uint32_t aBase[4]; int aS7[4];
#pragma unroll
        for (int mf = 0; mf < 4; mf++) {
            int r = mf * 16 + (lane & 15);
            aBase[mf] = (uint32_t)(r * 128);
            aS7[mf]   = r & 7;
        }
        uint32_t bBase[2]; int bS7[2];
#pragma unroll
        for (int p = 0; p < 2; p++) {
            int r = wn * 32 + p * 16 + ((lane >> 4) << 3) + (lane & 7);
            bBase[p] = (uint32_t)(G1_SUB_A + r * 128);
            bS7[p]   = r & 7;
        }

        float acc[4][4][4];
#pragma unroll
        for (int i = 0; i < 4; i++)
#pragma unroll
            for (int j = 0; j < 4; j++)
#pragma unroll
                for (int q = 0; q < 4; q++) acc[i][j][q] = 0.f;

        for (int k = 0; k < nc; ++k) {
            const int s  = k % G1_STAGES;
            const int ph = (k / G1_STAGES) & 1;
            const uint32_t st = tiles + s * G1_STAGE;
            MBAR_WAIT(sb + MB_FULL + 8 * s, ph);

#pragma unroll
            for (int ks = 0; ks < 4; ks++) {
                uint32_t b[2][4];
#pragma unroll
                for (int p = 0; p < 2; p++) {
                    uint32_t ad = st + bBase[p] + (uint32_t)((((ks * 2 + bHi) ^ bS7[p])) << 4);
                    LDSM_X4(b[p][0], b[p][1], b[p][2], b[p][3], ad);
                }
                uint32_t a[4][4];
#pragma unroll
                for (int mf = 0; mf < 4; mf++) {
                    uint32_t ad = st + aBase[mf] + (uint32_t)((((ks * 2 + aHi) ^ aS7[mf])) << 4);
                    LDSM_X4(a[mf][0], a[mf][1], a[mf][2], a[mf][3], ad);
                }
#pragma unroll
                for (int mf = 0; mf < 4; mf++)
#pragma unroll
                    for (int nf = 0; nf < 4; nf++)
                        MMA16816(acc[mf][nf],
                                 a[mf][0], a[mf][1], a[mf][2], a[mf][3],
                                 b[nf >> 1][(nf & 1) * 2], b[nf >> 1][(nf & 1) * 2 + 1]);
            }
            FENCE_ASYNC_SHARED();
            MBAR_ARRIVE(sb + MB_EMPTY + 8 * s);
        }

        const int q4 = lane >> 2;
        const int c2 = (lane & 3) * 2;
#pragma unroll
        for (int mf = 0; mf < 4; mf++) {
            const int rL0 = mf * 16 + q4;
#pragma unroll
            for (int nf = 0; nf < 4; nf++) {
                const int lc = wn * 32 + nf * 8 + c2;
                float s0 = scale_s[lc], s1 = scale_s[lc + 1];
                float bi0 = bias_s[lc], bi1 = bias_s[lc + 1];
                float y0 = fminf(1.f, fmaxf(-1.f, fmaf(acc[mf][nf][0], s0, bi0)));
                float y1 = fminf(1.f, fmaxf(-1.f, fmaf(acc[mf][nf][1], s1, bi1)));
                float y2 = fminf(1.f, fmaxf(-1.f, fmaf(acc[mf][nf][2], s0, bi0)));
                float y3 = fminf(1.f, fmaxf(-1.f, fmaf(acc[mf][nf][3], s1, bi1)));
                __half2 h01 = __floats2half2_rn(y0, y1);
                __half2 h23 = __floats2half2_rn(y2, y3);
                size_t base0 = (size_t)(m0 + rL0)     * HDIM + n0 + lc;
                size_t base1 = (size_t)(m0 + rL0 + 8) * HDIM + n0 + lc;
                *reinterpret_cast<__half2*>(g_h + base0) = h01;
                *reinterpret_cast<__half2*>(g_h + base1) = h23;
            }
        }
    }
}

// ---------------- GEMM2: TK=128, 2 stages, 2 CTAs/SM (R6 geometry + fence) ----------------
// partial[row] += clamp(...)*w_out[n]; write g_part[bx][row]
__global__ void __launch_bounds__(NTHREADS, 2)
gemm2_kernel(const __grid_constant__ CUtensorMap dA,
             const __grid_constant__ CUtensorMap dB,
             const float* __restrict__ log_scale,
             const float* __restrict__ bias,
             const float* __restrict__ w_out,
             int K) {
    extern __shared__ char smem_raw[];
    const uint32_t sb = smem_u32(smem_raw);
    const int tid  = threadIdx.x;
    const int wid  = tid >> 5;
    const int lane = tid & 31;
    const int m0 = blockIdx.y * TM;
    const int n0 = blockIdx.x * TN;
    const int nc = K / G2_TK;

    float* scale_s = (float*)(smem_raw + OFF_SCALE);
    float* bias_s  = (float*)(smem_raw + OFF_BIAS);
    float* w_s     = (float*)(smem_raw + OFF_W);
    float* red     = (float*)(smem_raw + OFF_RED);
    const uint32_t tiles = sb + G2_TILES;

    if (tid == 0) {
#pragma unroll
        for (int s = 0; s < G2_STAGES; s++) {
            MBAR_INIT(sb + MB_FULL  + 8 * s, 1);
            MBAR_INIT(sb + MB_EMPTY + 8 * s, NWARP_C * 32);
        }
        FENCE_ASYNC_SHARED();
    }
    if (tid < TN) {
        int j = n0 + tid;
        float z  = log_scale[j];
        float sp = fmaxf(z, 0.f) + log1pf(expf(-fabsf(z)));
        scale_s[tid] = fmaxf(sp, 1e-4f);
        bias_s[tid]  = bias[j];
        w_s[tid] = w_out[j];
    }
    __syncthreads();

    if (wid == NWARP_C) {
        if (lane == 0) {
            for (int k = 0; k < nc; k++) {
                int i = k / G2_STAGES;
                int s = k - i * G2_STAGES;
                uint32_t full  = sb + MB_FULL  + 8 * s;
                uint32_t empty = sb + MB_EMPTY + 8 * s;
                if (i > 0) MBAR_WAIT(empty, (i - 1) & 1);
                MBAR_EXPECT_TX(full, G2_STAGE);
                uint32_t st = tiles + s * G2_STAGE;
                TMA_LOAD_3D(st,                      &dA, k * G2_TK,      m0, 0, full);
                TMA_LOAD_3D(st + G2_SUB_A,           &dA, k * G2_TK + 64, m0, 0, full);
                TMA_LOAD_3D(st + 2 * G2_SUB_A,            &dB, k * G2_TK,      n0, 0, full);
                TMA_LOAD_3D(st + 2 * G2_SUB_A + G2_SUB_B, &dB, k * G2_TK + 64, n0, 0, full);
            }
        }
    } else {
        const int wn = wid;             // 0..3 (N)

        const int aHi = lane >> 4;
        const int bHi = (lane >> 3) & 1;
        uint32_t aBase[4]; int aS7[4];
#pragma unroll
        for (int mf = 0; mf < 4; mf++) {
            int r = mf * 16 + (lane & 15);
            aBase[mf] = (uint32_t)(r * 128);
            aS7[mf]   = r & 7;
        }
        uint32_t bBase[2]; int bS7[2];
#pragma unroll
        for (int p = 0; p < 2; p++) {
            int r = wn * 32 + p * 16 + ((lane >> 4) << 3) + (lane & 7);
            bBase[p] = (uint32_t)(r * 128);
            bS7[p]   = r & 7;
        }

        float acc[4][4][4];
#pragma unroll
        for (int i = 0; i < 4; i++)
#pragma unroll
            for (int j = 0; j < 4; j++)
#pragma unroll
                for (int q = 0; q < 4; q++) acc[i][j][q] = 0.f;

        for (int k = 0; k < nc; ++k) {
            const int s  = k % G2_STAGES;
            const int ph = (k / G2_STAGES) & 1;
            const uint32_t st = tiles + s * G2_STAGE;
            MBAR_WAIT(sb + MB_FULL + 8 * s, ph);

#pragma unroll
            for (int ks8 = 0; ks8 < 8; ks8++) {
                const int sub = ks8 >> 2;
                const int ksl = ks8 & 3;
                const uint32_t aT = st + sub * G2_SUB_A;
                const uint32_t bT = st + 2 * G2_SUB_A + sub * G2_SUB_B;
                uint32_t b[2][4];
#pragma unroll
                for (int p = 0; p < 2; p++) {
                    uint32_t ad = bT + bBase[p] + (uint32_t)((((ksl * 2 + bHi) ^ bS7[p])) << 4);
                    LDSM_X4(b[p][0], b[p][1], b[p][2], b[p][3], ad);
                }
                uint32_t a[4][4];
#pragma unroll
                for (int mf = 0; mf < 4; mf++) {
                    uint32_t ad = aT + aBase[mf] + (uint32_t)((((ksl * 2 + aHi) ^ aS7[mf])) << 4);
                    LDSM_X4(a[mf][0], a[mf][1], a[mf][2], a[mf][3], ad);
                }
#pragma unroll
                for (int mf = 0; mf < 4; mf++)
#pragma unroll
                    for (int nf = 0; nf < 4; nf++)
                        MMA16816(acc[mf][nf],
                                 a[mf][0], a[mf][1], a[mf][2], a[mf][3],
                                 b[nf >> 1][(nf & 1) * 2], b[nf >> 1][(nf & 1) * 2 + 1]);
            }
            FENCE_ASYNC_SHARED();
            MBAR_ARRIVE(sb + MB_EMPTY + 8 * s);
        }

        const int q4 = lane >> 2;
        const int c2 = (lane & 3) * 2;
#pragma unroll
        for (int mf = 0; mf < 4; mf++) {
            float pr0 = 0.f, pr1 = 0.f;
            const int rL0 = mf * 16 + q4;
#pragma unroll
            for (int nf = 0; nf < 4; nf++) {
                const int lc = wn * 32 + nf * 8 + c2;
                float s0 = scale_s[lc], s1 = scale_s[lc + 1];
                float bi0 = bias_s[lc], bi1 = bias_s[lc + 1];
                float y0 = fminf(1.f, fmaxf(-1.f, fmaf(acc[mf][nf][0], s0, bi0)));
                float y1 = fminf(1.f, fmaxf(-1.f, fmaf(acc[mf][nf][1], s1, bi1)));
                float y2 = fminf(1.f, fmaxf(-1.f, fmaf(acc[mf][nf][2], s0, bi0)));
                float y3 = fminf(1.f, fmaxf(-1.f, fmaf(acc[mf][nf][3], s1, bi1)));
                float w0 = w_s[lc], w1 = w_s[lc + 1];
                pr0 = fmaf(y0, w0, fmaf(y1, w1, pr0));
                pr1 = fmaf(y2, w0, fmaf(y3, w1, pr1));
            }
            pr0 += __shfl_xor_sync(0xffffffffu, pr0, 1);
            pr0 += __shfl_xor_sync(0xffffffffu, pr0, 2);
            pr1 += __shfl_xor_sync(0xffffffffu, pr1, 1);
            pr1 += __shfl_xor_sync(0xffffffffu, pr1, 2);
            if ((lane & 3) == 0) {
                red[(rL0)     * 4 + wn] = pr0;
                red[(rL0 + 8) * 4 + wn] = pr1;
            }
        }
    }
    __syncthreads();
    if (tid < TM) {
        float s = red[tid * 4 + 0] + red[tid * 4 + 1] +
                  red[tid * 4 + 2] + red[tid * 4 + 3];
        g_part[(size_t)blockIdx.x * BATCH + m0 + tid] = s;
    }
}

// ---------------- host launcher ----------------
typedef CUresult (*PFN_encodeTiled)(CUtensorMap*, CUtensorMapDataType, cuuint32_t,
                                    void*, const cuuint64_t*, const cuuint64_t*,
                                    const cuuint32_t*, const cuuint32_t*,
                                    CUtensorMapInterleave, CUtensorMapSwizzle,
                                    CUtensorMapL2promotion, CUtensorMapFloatOOBfill);

static void make_tmap(PFN_encodeTiled enc, CUtensorMap* m, void* ptr,
                      long long K, long long rows, unsigned box1) {
    cuuint64_t dims[3]    = {(cuuint64_t)K, (cuuint64_t)rows, 1};
    cuuint64_t strides[2] = {(cuuint64_t)(K * 2), (cuuint64_t)(K * rows * 2)};
    cuuint32_t box[3]     = {64, box1, 1};
    cuuint32_t es[3]      = {1, 1, 1};
    enc(m, CU_TENSOR_MAP_DATA_TYPE_FLOAT16, 3, ptr, dims, strides, box, es,
        CU_TENSOR_MAP_INTERLEAVE_NONE, CU_TENSOR_MAP_SWIZZLE_128B,
        CU_TENSOR_MAP_L2_PROMOTION_L2_128B, CU_TENSOR_MAP_FLOAT_OOB_FILL_NONE);
}

extern "C" void kernel_launch(void* const* d_in, const int* in_sizes, int n_in,
                              void* d_out, int out_size) {
    const float* x   = (const float*)d_in[0];
    const int*   st1 = (const int*)  d_in[1];
    const float* ls1 = (const float*)d_in[2];
    const float* b1  = (const float*)d_in[3];
    const int*   st2 = (const int*)  d_in[4];
    const float* ls2 = (const float*)d_in[5];
    const float* b2  = (const float*)d_in[6];
    const float* wo  = (const float*)d_in[7];
    const float* bo  = (const float*)d_in[8];
    float*       out = (float*)d_out;

    void *p_x, *p_s1, *p_s2, *p_h;
    cudaGetSymbolAddress(&p_x,  g_x);
    cudaGetSymbolAddress(&p_s1, g_s1);
    cudaGetSymbolAddress(&p_s2, g_s2);
    cudaGetSymbolAddress(&p_h,  g_h);

    PFN_encodeTiled enc = nullptr;
    cudaDriverEntryPointQueryResult qr;
    cudaGetDriverEntryPoint("cuTensorMapEncodeTiled", (void**)&enc,
                            cudaEnableDefault, &qr);
    if (!enc) return;

    CUtensorMap dA1, dB1, dA2, dB2;
    make_tmap(enc, &dA1, p_x,  IN_DIM, BATCH, TM);
    make_tmap(enc, &dB1, p_s1, IN_DIM, HDIM,  TN);
    make_tmap(enc, &dA2, p_h,  HDIM,   BATCH, TM);
    make_tmap(enc, &dB2, p_s2, HDIM,   HDIM,  TN);

    cudaFuncSetAttribute(gemm1_kernel,
                         cudaFuncAttributeMaxDynamicSharedMemorySize, G1_SMEM);
    cudaFuncSetAttribute(gemm2_kernel,
                         cudaFuncAttributeMaxDynamicSharedMemorySize, G2_SMEM);

    convert_all_kernel<<<(CVT_QUADS + 255) / 256, 256>>>(x, st1, st2);

    dim3 grid(NCOLT, BATCH / TM);   // (32, 256)
    gemm1_kernel<<<grid, NTHREADS, G1_SMEM>>>(dA1, dB1, ls1, b1, IN_DIM);
    gemm2_kernel<<<grid, NTHREADS, G2_SMEM>>>(dA2, dB2, ls2, b2, wo, HDIM);

    head_reduce_kernel<<<BATCH / 256, 256>>>(bo, out);
}